// round 1
// baseline (speedup 1.0000x reference)
#include <cuda_runtime.h>
#include <math.h>

// Problem constants
#define Bb 4
#define Ss 1024
#define Dd 1024
#define Hh 16
#define HDd 64
#define Ll 4
#define FFd 4096
#define NTOK (Bb * Ss)   // 4096

// ---------------- scratch (no allocations allowed) ----------------
__device__ float g_x[NTOK * Dd];        // residual stream        16 MB
__device__ float g_h[NTOK * Dd];        // normed activations     16 MB
__device__ float g_q[NTOK * Dd];        // 16 MB
__device__ float g_k[NTOK * Dd];        // 16 MB
__device__ float g_v[NTOK * Dd];        // 16 MB
__device__ float g_attn[NTOK * Dd];     // 16 MB
__device__ float g_ff[NTOK * FFd];      // 64 MB
__device__ float g_sc[(size_t)Bb * Hh * Ss * Ss];  // 256 MB attention scores

// ---------------- embedding + sinusoidal PE ----------------
__global__ void embed_kernel(const int* __restrict__ ids,
                             const float* __restrict__ emb,
                             float* __restrict__ x) {
    int t = blockIdx.x;            // token 0..NTOK-1
    int s = t & (Ss - 1);          // position within sequence
    int id = ids[t];
    const float c0 = -9.210340371976184f / (float)Dd;  // -ln(10000)/D
    for (int d = threadIdx.x; d < Dd; d += blockDim.x) {
        int pair = d & ~1;                       // 2*(d/2)
        float div = expf((float)pair * c0);
        float ang = (float)s * div;
        float pe = (d & 1) ? cosf(ang) : sinf(ang);
        x[(size_t)t * Dd + d] = emb[(size_t)id * Dd + d] + pe;
    }
}

// ---------------- layernorm: one block (256 thr) per token row ----------------
__global__ void ln_kernel(const float* __restrict__ x,
                          const float* __restrict__ g,
                          const float* __restrict__ b,
                          float* __restrict__ y) {
    int row = blockIdx.x;
    const float* xr = x + (size_t)row * Dd;
    float vals[4];
    float s = 0.f, sq = 0.f;
#pragma unroll
    for (int i = 0; i < 4; i++) {
        float t = xr[threadIdx.x + 256 * i];
        vals[i] = t; s += t; sq += t * t;
    }
#pragma unroll
    for (int o = 16; o; o >>= 1) {
        s  += __shfl_xor_sync(0xffffffffu, s, o);
        sq += __shfl_xor_sync(0xffffffffu, sq, o);
    }
    __shared__ float ss[8], ssq[8];
    int w = threadIdx.x >> 5, lane = threadIdx.x & 31;
    if (lane == 0) { ss[w] = s; ssq[w] = sq; }
    __syncthreads();
    if (w == 0) {
        s  = (lane < 8) ? ss[lane]  : 0.f;
        sq = (lane < 8) ? ssq[lane] : 0.f;
#pragma unroll
        for (int o = 4; o; o >>= 1) {
            s  += __shfl_xor_sync(0xffffffffu, s, o);
            sq += __shfl_xor_sync(0xffffffffu, sq, o);
        }
        if (lane == 0) { ss[0] = s; ssq[0] = sq; }
    }
    __syncthreads();
    float mean = ss[0] * (1.f / Dd);
    float var  = ssq[0] * (1.f / Dd) - mean * mean;
    float inv  = rsqrtf(var + 1e-5f);
#pragma unroll
    for (int i = 0; i < 4; i++) {
        int c = threadIdx.x + 256 * i;
        y[(size_t)row * Dd + c] = (vals[i] - mean) * inv * g[c] + b[c];
    }
}

// ---------------- generic tiled GEMM: C = A[M,K] @ W[K,N] + bias (+gelu)(+res) ----------------
// 64x64 tile, BK=16, 256 threads, 4x4 micro-tile
template <bool GELU, bool RES>
__global__ void gemm_kernel(const float* __restrict__ A,
                            const float* __restrict__ W,
                            const float* __restrict__ bias,
                            const float* __restrict__ res,
                            float* __restrict__ C,
                            int M, int N, int K) {
    __shared__ float As[16][65];   // As[kk][m]
    __shared__ float Bs[16][65];   // Bs[kk][n]
    int bm = blockIdx.y * 64, bn = blockIdx.x * 64;
    int tx = threadIdx.x & 15, ty = threadIdx.x >> 4;
    float acc[4][4] = {};
    for (int k0 = 0; k0 < K; k0 += 16) {
#pragma unroll
        for (int i = threadIdx.x; i < 64 * 16; i += 256) {
            int m = i >> 4, kk = i & 15;
            As[kk][m] = A[(size_t)(bm + m) * K + k0 + kk];
        }
#pragma unroll
        for (int i = threadIdx.x; i < 16 * 64; i += 256) {
            int kk = i >> 6, n = i & 63;
            Bs[kk][n] = W[(size_t)(k0 + kk) * N + bn + n];
        }
        __syncthreads();
#pragma unroll
        for (int kk = 0; kk < 16; kk++) {
            float a[4], bvv[4];
#pragma unroll
            for (int i = 0; i < 4; i++) a[i] = As[kk][ty * 4 + i];
#pragma unroll
            for (int j = 0; j < 4; j++) bvv[j] = Bs[kk][tx * 4 + j];
#pragma unroll
            for (int i = 0; i < 4; i++)
#pragma unroll
                for (int j = 0; j < 4; j++) acc[i][j] += a[i] * bvv[j];
        }
        __syncthreads();
    }
#pragma unroll
    for (int i = 0; i < 4; i++) {
        int r = bm + ty * 4 + i;
#pragma unroll
        for (int j = 0; j < 4; j++) {
            int c = bn + tx * 4 + j;
            float val = acc[i][j] + bias[c];
            if (GELU) val = 0.5f * val * (1.f + erff(val * 0.70710678118654752f));
            if (RES)  val += res[(size_t)r * N + c];
            C[(size_t)r * N + c] = val;
        }
    }
}

// ---------------- QK^T with scale + causal + key-mask epilogue ----------------
// grid (S/64, S/64, B*H); per-(b,h) GEMM: scores[q,k] = Q[q,:64] . K[k,:64]
__global__ void qk_kernel(const float* __restrict__ q,
                          const float* __restrict__ k,
                          const int* __restrict__ am,
                          float* __restrict__ sc) {
    int bh = blockIdx.z;
    int b = bh >> 4, h = bh & 15;
    int bm = blockIdx.y * 64, bn = blockIdx.x * 64;
    float* out = sc + (size_t)bh * Ss * Ss;
    if (bn > bm + 63) {                 // tile fully above diagonal: all -inf
        for (int i = threadIdx.x; i < 64 * 64; i += 256) {
            int r = i >> 6, c = i & 63;
            out[(size_t)(bm + r) * Ss + bn + c] = -INFINITY;
        }
        return;
    }
    __shared__ float Qs[64][65];        // Qs[row][kk]
    __shared__ float KsT[64][65];       // KsT[kk][keyrow]
    const float* qb = q + (size_t)b * Ss * Dd + h * HDd;
    const float* kb = k + (size_t)b * Ss * Dd + h * HDd;
    for (int i = threadIdx.x; i < 64 * 64; i += 256) {
        int r = i >> 6, c = i & 63;
        Qs[r][c]  = qb[(size_t)(bm + r) * Dd + c];
        KsT[c][r] = kb[(size_t)(bn + r) * Dd + c];
    }
    __syncthreads();
    int tx = threadIdx.x & 15, ty = threadIdx.x >> 4;
    float acc[4][4] = {};
#pragma unroll
    for (int kk = 0; kk < 64; kk++) {
        float a[4], bvv[4];
#pragma unroll
        for (int i = 0; i < 4; i++) a[i] = Qs[ty * 4 + i][kk];
#pragma unroll
        for (int j = 0; j < 4; j++) bvv[j] = KsT[kk][tx * 4 + j];
#pragma unroll
        for (int i = 0; i < 4; i++)
#pragma unroll
            for (int j = 0; j < 4; j++) acc[i][j] += a[i] * bvv[j];
    }
    const float scale = 0.125f;         // 1/sqrt(64)
#pragma unroll
    for (int i = 0; i < 4; i++) {
        int r = bm + ty * 4 + i;
#pragma unroll
        for (int j = 0; j < 4; j++) {
            int c = bn + tx * 4 + j;
            float v = (c <= r && am[b * Ss + c] != 0) ? acc[i][j] * scale : -INFINITY;
            out[(size_t)r * Ss + c] = v;
        }
    }
}

// ---------------- row softmax over S=1024, with nan_to_num semantics ----------------
__global__ void softmax_kernel(float* __restrict__ sc) {
    float* r = sc + (size_t)blockIdx.x * Ss;
    float v[4];
    float mx = -INFINITY;
#pragma unroll
    for (int i = 0; i < 4; i++) { v[i] = r[threadIdx.x + 256 * i]; mx = fmaxf(mx, v[i]); }
#pragma unroll
    for (int o = 16; o; o >>= 1) mx = fmaxf(mx, __shfl_xor_sync(0xffffffffu, mx, o));
    __shared__ float sm[8];
    int w = threadIdx.x >> 5, lane = threadIdx.x & 31;
    if (lane == 0) sm[w] = mx;
    __syncthreads();
    if (w == 0) {
        mx = (lane < 8) ? sm[lane] : -INFINITY;
#pragma unroll
        for (int o = 4; o; o >>= 1) mx = fmaxf(mx, __shfl_xor_sync(0xffffffffu, mx, o));
        if (lane == 0) sm[0] = mx;
    }
    __syncthreads();
    mx = sm[0];
    if (mx == -INFINITY) {              // fully-masked row -> zeros (nan_to_num)
#pragma unroll
        for (int i = 0; i < 4; i++) r[threadIdx.x + 256 * i] = 0.f;
        return;
    }
    float s = 0.f;
#pragma unroll
    for (int i = 0; i < 4; i++) { v[i] = expf(v[i] - mx); s += v[i]; }
#pragma unroll
    for (int o = 16; o; o >>= 1) s += __shfl_xor_sync(0xffffffffu, s, o);
    __shared__ float ssum[8];
    if (lane == 0) ssum[w] = s;
    __syncthreads();
    if (w == 0) {
        s = (lane < 8) ? ssum[lane] : 0.f;
#pragma unroll
        for (int o = 4; o; o >>= 1) s += __shfl_xor_sync(0xffffffffu, s, o);
        if (lane == 0) ssum[0] = s;
    }
    __syncthreads();
    float inv = 1.f / ssum[0];
#pragma unroll
    for (int i = 0; i < 4; i++) r[threadIdx.x + 256 * i] = v[i] * inv;
}

// ---------------- P @ V (causal-truncated K loop) ----------------
// grid (S/64, B*H): C[64 rows, 64 head-dims] = P[64, keys<=bm+63] @ V
__global__ void pv_kernel(const float* __restrict__ sc,
                          const float* __restrict__ v,
                          float* __restrict__ attn) {
    int bh = blockIdx.y;
    int b = bh >> 4, h = bh & 15;
    int bm = blockIdx.x * 64;
    int kmax = bm + 64;                 // keys beyond have prob 0
    __shared__ float Ps[64][33];        // Ps[row][kk]
    __shared__ float Vs[32][65];        // Vs[kk][dim]
    const float* srow = sc + (size_t)bh * Ss * Ss;
    const float* vb = v + (size_t)b * Ss * Dd + h * HDd;
    int tx = threadIdx.x & 15, ty = threadIdx.x >> 4;
    float acc[4][4] = {};
    for (int k0 = 0; k0 < kmax; k0 += 32) {
        for (int i = threadIdx.x; i < 64 * 32; i += 256) {
            int r = i >> 5, c = i & 31;
            Ps[r][c] = srow[(size_t)(bm + r) * Ss + k0 + c];
        }
        for (int i = threadIdx.x; i < 32 * 64; i += 256) {
            int r = i >> 6, c = i & 63;
            Vs[r][c] = vb[(size_t)(k0 + r) * Dd + c];
        }
        __syncthreads();
#pragma unroll
        for (int kk = 0; kk < 32; kk++) {
            float a[4], bvv[4];
#pragma unroll
            for (int i = 0; i < 4; i++) a[i] = Ps[ty * 4 + i][kk];
#pragma unroll
            for (int j = 0; j < 4; j++) bvv[j] = Vs[kk][tx * 4 + j];
#pragma unroll
            for (int i = 0; i < 4; i++)
#pragma unroll
                for (int j = 0; j < 4; j++) acc[i][j] += a[i] * bvv[j];
        }
        __syncthreads();
    }
#pragma unroll
    for (int i = 0; i < 4; i++) {
        int r = bm + ty * 4 + i;
#pragma unroll
        for (int j = 0; j < 4; j++) {
            int c = tx * 4 + j;
            attn[((size_t)b * Ss + r) * Dd + h * HDd + c] = acc[i][j];
        }
    }
}

// ---------------- launch ----------------
extern "C" void kernel_launch(void* const* d_in, const int* in_sizes, int n_in,
                              void* d_out, int out_size) {
    const int*   ids  = (const int*)d_in[0];
    const int*   am   = (const int*)d_in[1];
    const float* emb  = (const float*)d_in[2];
    const float* ln1g = (const float*)d_in[3];
    const float* ln1b = (const float*)d_in[4];
    const float* wq   = (const float*)d_in[5];
    const float* bq   = (const float*)d_in[6];
    const float* wk   = (const float*)d_in[7];
    const float* bk   = (const float*)d_in[8];
    const float* wv   = (const float*)d_in[9];
    const float* bv   = (const float*)d_in[10];
    const float* wo   = (const float*)d_in[11];
    const float* bo   = (const float*)d_in[12];
    const float* ln2g = (const float*)d_in[13];
    const float* ln2b = (const float*)d_in[14];
    const float* w1   = (const float*)d_in[15];
    const float* b1   = (const float*)d_in[16];
    const float* w2   = (const float*)d_in[17];
    const float* b2   = (const float*)d_in[18];
    const float* lnfg = (const float*)d_in[19];
    const float* lnfb = (const float*)d_in[20];

    float *x, *h, *q, *k, *v, *attn, *ff, *sc;
    cudaGetSymbolAddress((void**)&x, g_x);
    cudaGetSymbolAddress((void**)&h, g_h);
    cudaGetSymbolAddress((void**)&q, g_q);
    cudaGetSymbolAddress((void**)&k, g_k);
    cudaGetSymbolAddress((void**)&v, g_v);
    cudaGetSymbolAddress((void**)&attn, g_attn);
    cudaGetSymbolAddress((void**)&ff, g_ff);
    cudaGetSymbolAddress((void**)&sc, g_sc);

    embed_kernel<<<NTOK, 256>>>(ids, emb, x);

    dim3 gProj(Dd / 64, NTOK / 64);     // N=1024 GEMMs
    dim3 gFF1(FFd / 64, NTOK / 64);     // N=4096 GEMM
    dim3 gQK(Ss / 64, Ss / 64, Bb * Hh);
    dim3 gPV(Ss / 64, Bb * Hh);

    for (int l = 0; l < Ll; l++) {
        size_t wOff = (size_t)l * Dd * Dd;
        ln_kernel<<<NTOK, 256>>>(x, ln1g + l * Dd, ln1b + l * Dd, h);
        gemm_kernel<false, false><<<gProj, 256>>>(h, wq + wOff, bq + l * Dd, nullptr, q, NTOK, Dd, Dd);
        gemm_kernel<false, false><<<gProj, 256>>>(h, wk + wOff, bk + l * Dd, nullptr, k, NTOK, Dd, Dd);
        gemm_kernel<false, false><<<gProj, 256>>>(h, wv + wOff, bv + l * Dd, nullptr, v, NTOK, Dd, Dd);
        qk_kernel<<<gQK, 256>>>(q, k, am, sc);
        softmax_kernel<<<Bb * Hh * Ss, 256>>>(sc);
        pv_kernel<<<gPV, 256>>>(sc, v, attn);
        gemm_kernel<false, true><<<gProj, 256>>>(attn, wo + wOff, bo + l * Dd, x, x, NTOK, Dd, Dd);
        ln_kernel<<<NTOK, 256>>>(x, ln2g + l * Dd, ln2b + l * Dd, h);
        gemm_kernel<true, false><<<gFF1, 256>>>(h, w1 + (size_t)l * Dd * FFd, b1 + l * FFd, nullptr, ff, NTOK, FFd, Dd);
        gemm_kernel<false, true><<<gProj, 256>>>(ff, w2 + (size_t)l * FFd * Dd, b2 + l * Dd, x, x, NTOK, Dd, FFd);
    }
    ln_kernel<<<NTOK, 256>>>(x, lnfg, lnfb, (float*)d_out);
}

// round 4
// speedup vs baseline: 2.6289x; 2.6289x over previous
#include <cuda_runtime.h>
#include <cuda_bf16.h>
#include <math.h>
#include <stdint.h>

typedef __nv_bfloat16 bf16;

#define Bb 4
#define Ss 1024
#define Dd 1024
#define Hh 16
#define HDd 64
#define Ll 4
#define FFd 4096
#define NTOK (Bb * Ss)   // 4096

// ================= scratch (no allocations allowed) =================
__device__ float g_x[NTOK * Dd];                         // residual stream
__device__ unsigned short g_hhi[NTOK * Dd];              // normed act hi
__device__ unsigned short g_hlo[NTOK * Dd];              // normed act lo
__device__ float g_q[NTOK * Dd];
__device__ float g_k[NTOK * Dd];
__device__ float g_v[NTOK * Dd];
__device__ unsigned short g_athi[NTOK * Dd];             // attn out hi
__device__ unsigned short g_atlo[NTOK * Dd];             // attn out lo
__device__ unsigned short g_ffhi[NTOK * FFd];            // ff hidden hi
__device__ unsigned short g_fflo[NTOK * FFd];            // ff hidden lo
__device__ unsigned short g_wthi[Dd * FFd];              // transposed weight hi
__device__ unsigned short g_wtlo[Dd * FFd];              // transposed weight lo
__device__ float g_sc[(size_t)Bb * Hh * Ss * Ss];        // attention scores

// ================= mma.sync helpers =================
__device__ __forceinline__ uint32_t smem_u32(const void* p) {
    uint32_t a;
    asm("{ .reg .u64 t; cvta.to.shared.u64 t, %1; cvt.u32.u64 %0, t; }" : "=r"(a) : "l"(p));
    return a;
}
__device__ __forceinline__ void ldsm4(uint32_t* r, uint32_t addr) {
    asm volatile("ldmatrix.sync.aligned.m8n8.x4.shared.b16 {%0,%1,%2,%3}, [%4];"
        : "=r"(r[0]), "=r"(r[1]), "=r"(r[2]), "=r"(r[3]) : "r"(addr));
}
__device__ __forceinline__ void mma16816(float* c, const uint32_t* a, const uint32_t* b) {
    asm volatile("mma.sync.aligned.m16n8k16.row.col.f32.bf16.bf16.f32 "
        "{%0,%1,%2,%3}, {%4,%5,%6,%7}, {%8,%9}, {%0,%1,%2,%3};"
        : "+f"(c[0]), "+f"(c[1]), "+f"(c[2]), "+f"(c[3])
        : "r"(a[0]), "r"(a[1]), "r"(a[2]), "r"(a[3]), "r"(b[0]), "r"(b[1]));
}

// ================= split-bf16 GEMM via mma.sync =================
// C[M,N] = (Ahi+Alo)[M,K] @ (Bhi+Blo)^T, B stored [N][K] K-major (= col-major B).
// Block 128x128, BK=32, 256 threads (8 warps, 2x4), warp tile 64x32.
#define LDS 40   // smem row stride in bf16 (32 data + 8 pad -> 80B rows)

template <bool GELU, bool RES, bool OUTSPLIT>
__global__ __launch_bounds__(256) void mma_gemm(
        const bf16* __restrict__ Ahi, const bf16* __restrict__ Alo,
        const bf16* __restrict__ Bhi, const bf16* __restrict__ Blo,
        const float* __restrict__ bias, const float* __restrict__ res,
        float* __restrict__ C, bf16* __restrict__ Chi, bf16* __restrict__ Clo,
        int M, int N, int K) {
    __shared__ bf16 sAh[128][LDS], sAl[128][LDS], sBh[128][LDS], sBl[128][LDS];

    const int tid = threadIdx.x, lane = tid & 31, wid = tid >> 5;
    const int warp_m = wid & 1, warp_n = wid >> 1;        // 2 x 4 warp grid
    const int bm = blockIdx.y * 128, bn = blockIdx.x * 128;

    float acc[4][4][4] = {};   // [mtile][ntile][frag]

    // register-staged global prefetch (2 rows of uint4 per array per thread)
    uint4 ra_h[2], ra_l[2], rb_h[2], rb_l[2];
    const int nchunk = K >> 5;

    auto gload = [&](int c) {
#pragma unroll
        for (int i = 0; i < 2; i++) {
            int idx = tid + i * 256;
            int row = idx >> 2, seg = idx & 3;
            size_t ga = (size_t)(bm + row) * K + c * 32 + seg * 8;
            size_t gb = (size_t)(bn + row) * K + c * 32 + seg * 8;
            ra_h[i] = *(const uint4*)(Ahi + ga);
            ra_l[i] = *(const uint4*)(Alo + ga);
            rb_h[i] = *(const uint4*)(Bhi + gb);
            rb_l[i] = *(const uint4*)(Blo + gb);
        }
    };
    auto sstore = [&]() {
#pragma unroll
        for (int i = 0; i < 2; i++) {
            int idx = tid + i * 256;
            int row = idx >> 2, seg = idx & 3;
            *(uint4*)&sAh[row][seg * 8] = ra_h[i];
            *(uint4*)&sAl[row][seg * 8] = ra_l[i];
            *(uint4*)&sBh[row][seg * 8] = rb_h[i];
            *(uint4*)&sBl[row][seg * 8] = rb_l[i];
        }
    };

    // ldmatrix lane addressing
    const int arow = warp_m * 64 + (lane & 7) + ((lane >> 3) & 1) * 8;
    const int acol = (lane >> 4) * 8;                  // 0 or 8 (k within 16)
    const int brow = warp_n * 32 + (lane & 7) + (lane >> 4) * 8;
    const int bcol = ((lane >> 3) & 1) * 8;

    const uint32_t sah = smem_u32(&sAh[0][0]), sal = smem_u32(&sAl[0][0]);
    const uint32_t sbh = smem_u32(&sBh[0][0]), sbl = smem_u32(&sBl[0][0]);

    gload(0);
    for (int c = 0; c < nchunk; c++) {
        sstore();
        __syncthreads();
        if (c + 1 < nchunk) gload(c + 1);
#pragma unroll
        for (int k16 = 0; k16 < 2; k16++) {
            uint32_t ah[4][4], al[4][4], bh[4][2], bl[4][2];
#pragma unroll
            for (int mt = 0; mt < 4; mt++) {
                uint32_t off = (uint32_t)((arow + mt * 16) * LDS + k16 * 16 + acol) * 2;
                ldsm4(ah[mt], sah + off);
                ldsm4(al[mt], sal + off);
            }
#pragma unroll
            for (int nt2 = 0; nt2 < 2; nt2++) {
                uint32_t off = (uint32_t)((brow + nt2 * 16) * LDS + k16 * 16 + bcol) * 2;
                uint32_t t[4];
                ldsm4(t, sbh + off);
                bh[nt2 * 2 + 0][0] = t[0]; bh[nt2 * 2 + 0][1] = t[1];
                bh[nt2 * 2 + 1][0] = t[2]; bh[nt2 * 2 + 1][1] = t[3];
                ldsm4(t, sbl + off);
                bl[nt2 * 2 + 0][0] = t[0]; bl[nt2 * 2 + 0][1] = t[1];
                bl[nt2 * 2 + 1][0] = t[2]; bl[nt2 * 2 + 1][1] = t[3];
            }
#pragma unroll
            for (int mt = 0; mt < 4; mt++)
#pragma unroll
                for (int nt = 0; nt < 4; nt++) {
                    mma16816(acc[mt][nt], ah[mt], bh[nt]);
                    mma16816(acc[mt][nt], ah[mt], bl[nt]);
                    mma16816(acc[mt][nt], al[mt], bh[nt]);
                }
        }
        __syncthreads();
    }

    // ---- epilogue: fragment -> global, fused bias/gelu/res/split ----
#pragma unroll
    for (int mt = 0; mt < 4; mt++) {
#pragma unroll
        for (int nt = 0; nt < 4; nt++) {
            int r0 = bm + warp_m * 64 + mt * 16 + (lane >> 2);
            int c0 = bn + warp_n * 32 + nt * 8 + (lane & 3) * 2;
#pragma unroll
            for (int half = 0; half < 2; half++) {       // c0/c1 then c2/c3 (row+8)
                int r = r0 + half * 8;
#pragma unroll
                for (int e = 0; e < 2; e++) {
                    int cc = c0 + e;
                    float v = acc[mt][nt][half * 2 + e] + bias[cc];
                    if (GELU) v = 0.5f * v * (1.f + erff(v * 0.70710678118654752f));
                    if (RES)  v += res[(size_t)r * N + cc];
                    size_t o = (size_t)r * N + cc;
                    if (OUTSPLIT) {
                        bf16 hv = __float2bfloat16(v);
                        Chi[o] = hv;
                        Clo[o] = __float2bfloat16(v - __bfloat162float(hv));
                    } else {
                        C[o] = v;
                    }
                }
            }
        }
    }
}

// ================= weight transpose + bf16 split: Wt[n][k] = W[k][n] =================
__global__ void transpose_split(const float* __restrict__ W, bf16* __restrict__ Thi,
                                bf16* __restrict__ Tlo, int K, int N) {
    __shared__ float t[32][33];
    int bk = blockIdx.y * 32, bn = blockIdx.x * 32;
    int tx = threadIdx.x & 31, ty = threadIdx.x >> 5;
#pragma unroll
    for (int i = 0; i < 32; i += 8)
        t[ty + i][tx] = W[(size_t)(bk + ty + i) * N + bn + tx];
    __syncthreads();
#pragma unroll
    for (int i = 0; i < 32; i += 8) {
        float v = t[tx][ty + i];
        size_t o = (size_t)(bn + ty + i) * K + bk + tx;
        bf16 h = __float2bfloat16(v);
        Thi[o] = h;
        Tlo[o] = __float2bfloat16(v - __bfloat162float(h));
    }
}

// ================= embedding + sinusoidal PE =================
__global__ void embed_kernel(const int* __restrict__ ids, const float* __restrict__ emb,
                             float* __restrict__ x) {
    int t = blockIdx.x;
    int s = t & (Ss - 1);
    int id = ids[t];
    const float c0 = -9.210340371976184f / (float)Dd;
    for (int d = threadIdx.x; d < Dd; d += blockDim.x) {
        int pair = d & ~1;
        float div = expf((float)pair * c0);
        float ang = (float)s * div;
        float pe = (d & 1) ? cosf(ang) : sinf(ang);
        x[(size_t)t * Dd + d] = emb[(size_t)id * Dd + d] + pe;
    }
}

// ================= layernorm (optionally emitting bf16 hi/lo split) =================
template <bool SPLIT>
__global__ void ln_kernel(const float* __restrict__ x, const float* __restrict__ g,
                          const float* __restrict__ b, float* __restrict__ y,
                          bf16* __restrict__ yhi, bf16* __restrict__ ylo) {
    int row = blockIdx.x;
    const float* xr = x + (size_t)row * Dd;
    float vals[4];
    float s = 0.f, sq = 0.f;
#pragma unroll
    for (int i = 0; i < 4; i++) {
        float t = xr[threadIdx.x + 256 * i];
        vals[i] = t; s += t; sq += t * t;
    }
#pragma unroll
    for (int o = 16; o; o >>= 1) {
        s  += __shfl_xor_sync(0xffffffffu, s, o);
        sq += __shfl_xor_sync(0xffffffffu, sq, o);
    }
    __shared__ float ss[8], ssq[8];
    int w = threadIdx.x >> 5, lane = threadIdx.x & 31;
    if (lane == 0) { ss[w] = s; ssq[w] = sq; }
    __syncthreads();
    if (w == 0) {
        s  = (lane < 8) ? ss[lane]  : 0.f;
        sq = (lane < 8) ? ssq[lane] : 0.f;
#pragma unroll
        for (int o = 4; o; o >>= 1) {
            s  += __shfl_xor_sync(0xffffffffu, s, o);
            sq += __shfl_xor_sync(0xffffffffu, sq, o);
        }
        if (lane == 0) { ss[0] = s; ssq[0] = sq; }
    }
    __syncthreads();
    float mean = ss[0] * (1.f / Dd);
    float var  = ssq[0] * (1.f / Dd) - mean * mean;
    float inv  = rsqrtf(var + 1e-5f);
#pragma unroll
    for (int i = 0; i < 4; i++) {
        int c = threadIdx.x + 256 * i;
        float v = (vals[i] - mean) * inv * g[c] + b[c];
        size_t o = (size_t)row * Dd + c;
        if (SPLIT) {
            bf16 h = __float2bfloat16(v);
            yhi[o] = h;
            ylo[o] = __float2bfloat16(v - __bfloat162float(h));
        } else {
            y[o] = v;
        }
    }
}

// ================= QK^T with scale + causal + key-mask =================
__global__ void qk_kernel(const float* __restrict__ q, const float* __restrict__ k,
                          const int* __restrict__ am, float* __restrict__ sc) {
    int bh = blockIdx.z;
    int b = bh >> 4, h = bh & 15;
    int bm = blockIdx.y * 64, bn = blockIdx.x * 64;
    float* out = sc + (size_t)bh * Ss * Ss;
    if (bn > bm + 63) {
        for (int i = threadIdx.x; i < 64 * 64; i += 256) {
            int r = i >> 6, c = i & 63;
            out[(size_t)(bm + r) * Ss + bn + c] = -INFINITY;
        }
        return;
    }
    __shared__ float Qs[64][65];
    __shared__ float KsT[64][65];
    const float* qb = q + (size_t)b * Ss * Dd + h * HDd;
    const float* kb = k + (size_t)b * Ss * Dd + h * HDd;
    for (int i = threadIdx.x; i < 64 * 64; i += 256) {
        int r = i >> 6, c = i & 63;
        Qs[r][c]  = qb[(size_t)(bm + r) * Dd + c];
        KsT[c][r] = kb[(size_t)(bn + r) * Dd + c];
    }
    __syncthreads();
    int tx = threadIdx.x & 15, ty = threadIdx.x >> 4;
    float acc[4][4] = {};
#pragma unroll
    for (int kk = 0; kk < 64; kk++) {
        float a[4], bvv[4];
#pragma unroll
        for (int i = 0; i < 4; i++) a[i] = Qs[ty * 4 + i][kk];
#pragma unroll
        for (int j = 0; j < 4; j++) bvv[j] = KsT[kk][tx * 4 + j];
#pragma unroll
        for (int i = 0; i < 4; i++)
#pragma unroll
            for (int j = 0; j < 4; j++) acc[i][j] += a[i] * bvv[j];
    }
    const float scale = 0.125f;
#pragma unroll
    for (int i = 0; i < 4; i++) {
        int r = bm + ty * 4 + i;
#pragma unroll
        for (int j = 0; j < 4; j++) {
            int c = bn + tx * 4 + j;
            float v = (c <= r && am[b * Ss + c] != 0) ? acc[i][j] * scale : -INFINITY;
            out[(size_t)r * Ss + c] = v;
        }
    }
}

// ================= row softmax over S=1024 =================
__global__ void softmax_kernel(float* __restrict__ sc) {
    float* r = sc + (size_t)blockIdx.x * Ss;
    float v[4];
    float mx = -INFINITY;
#pragma unroll
    for (int i = 0; i < 4; i++) { v[i] = r[threadIdx.x + 256 * i]; mx = fmaxf(mx, v[i]); }
#pragma unroll
    for (int o = 16; o; o >>= 1) mx = fmaxf(mx, __shfl_xor_sync(0xffffffffu, mx, o));
    __shared__ float sm[8];
    int w = threadIdx.x >> 5, lane = threadIdx.x & 31;
    if (lane == 0) sm[w] = mx;
    __syncthreads();
    if (w == 0) {
        mx = (lane < 8) ? sm[lane] : -INFINITY;
#pragma unroll
        for (int o = 4; o; o >>= 1) mx = fmaxf(mx, __shfl_xor_sync(0xffffffffu, mx, o));
        if (lane == 0) sm[0] = mx;
    }
    __syncthreads();
    mx = sm[0];
    if (mx == -INFINITY) {
#pragma unroll
        for (int i = 0; i < 4; i++) r[threadIdx.x + 256 * i] = 0.f;
        return;
    }
    float s = 0.f;
#pragma unroll
    for (int i = 0; i < 4; i++) { v[i] = expf(v[i] - mx); s += v[i]; }
#pragma unroll
    for (int o = 16; o; o >>= 1) s += __shfl_xor_sync(0xffffffffu, s, o);
    __shared__ float ssum[8];
    if (lane == 0) ssum[w] = s;
    __syncthreads();
    if (w == 0) {
        s = (lane < 8) ? ssum[lane] : 0.f;
#pragma unroll
        for (int o = 4; o; o >>= 1) s += __shfl_xor_sync(0xffffffffu, s, o);
        if (lane == 0) ssum[0] = s;
    }
    __syncthreads();
    float inv = 1.f / ssum[0];
#pragma unroll
    for (int i = 0; i < 4; i++) r[threadIdx.x + 256 * i] = v[i] * inv;
}

// ================= P @ V, emitting bf16 hi/lo split =================
__global__ void pv_kernel(const float* __restrict__ sc, const float* __restrict__ v,
                          bf16* __restrict__ ahi, bf16* __restrict__ alo) {
    int bh = blockIdx.y;
    int b = bh >> 4, h = bh & 15;
    int bm = blockIdx.x * 64;
    int kmax = bm + 64;
    __shared__ float Ps[64][33];
    __shared__ float Vs[32][65];
    const float* srow = sc + (size_t)bh * Ss * Ss;
    const float* vb = v + (size_t)b * Ss * Dd + h * HDd;
    int tx = threadIdx.x & 15, ty = threadIdx.x >> 4;
    float acc[4][4] = {};
    for (int k0 = 0; k0 < kmax; k0 += 32) {
        for (int i = threadIdx.x; i < 64 * 32; i += 256) {
            int r = i >> 5, c = i & 31;
            Ps[r][c] = srow[(size_t)(bm + r) * Ss + k0 + c];
        }
        for (int i = threadIdx.x; i < 32 * 64; i += 256) {
            int r = i >> 6, c = i & 63;
            Vs[r][c] = vb[(size_t)(k0 + r) * Dd + c];
        }
        __syncthreads();
#pragma unroll
        for (int kk = 0; kk < 32; kk++) {
            float a[4], bvv[4];
#pragma unroll
            for (int i = 0; i < 4; i++) a[i] = Ps[ty * 4 + i][kk];
#pragma unroll
            for (int j = 0; j < 4; j++) bvv[j] = Vs[kk][tx * 4 + j];
#pragma unroll
            for (int i = 0; i < 4; i++)
#pragma unroll
                for (int j = 0; j < 4; j++) acc[i][j] += a[i] * bvv[j];
        }
        __syncthreads();
    }
#pragma unroll
    for (int i = 0; i < 4; i++) {
        int r = bm + ty * 4 + i;
#pragma unroll
        for (int j = 0; j < 4; j++) {
            int c = tx * 4 + j;
            size_t o = ((size_t)b * Ss + r) * Dd + h * HDd + c;
            float val = acc[i][j];
            bf16 hv = __float2bfloat16(val);
            ahi[o] = hv;
            alo[o] = __float2bfloat16(val - __bfloat162float(hv));
        }
    }
}

// ================= launch =================
extern "C" void kernel_launch(void* const* d_in, const int* in_sizes, int n_in,
                              void* d_out, int out_size) {
    const int*   ids  = (const int*)d_in[0];
    const int*   am   = (const int*)d_in[1];
    const float* emb  = (const float*)d_in[2];
    const float* ln1g = (const float*)d_in[3];
    const float* ln1b = (const float*)d_in[4];
    const float* wq   = (const float*)d_in[5];
    const float* bq   = (const float*)d_in[6];
    const float* wk   = (const float*)d_in[7];
    const float* bk   = (const float*)d_in[8];
    const float* wv   = (const float*)d_in[9];
    const float* bv   = (const float*)d_in[10];
    const float* wo   = (const float*)d_in[11];
    const float* bo   = (const float*)d_in[12];
    const float* ln2g = (const float*)d_in[13];
    const float* ln2b = (const float*)d_in[14];
    const float* w1   = (const float*)d_in[15];
    const float* b1   = (const float*)d_in[16];
    const float* w2   = (const float*)d_in[17];
    const float* b2   = (const float*)d_in[18];
    const float* lnfg = (const float*)d_in[19];
    const float* lnfb = (const float*)d_in[20];

    float *x, *q, *k, *v, *sc;
    bf16 *hhi, *hlo, *athi, *atlo, *ffhi, *fflo, *wthi, *wtlo;
    cudaGetSymbolAddress((void**)&x, g_x);
    cudaGetSymbolAddress((void**)&q, g_q);
    cudaGetSymbolAddress((void**)&k, g_k);
    cudaGetSymbolAddress((void**)&v, g_v);
    cudaGetSymbolAddress((void**)&sc, g_sc);
    cudaGetSymbolAddress((void**)&hhi, g_hhi);
    cudaGetSymbolAddress((void**)&hlo, g_hlo);
    cudaGetSymbolAddress((void**)&athi, g_athi);
    cudaGetSymbolAddress((void**)&atlo, g_atlo);
    cudaGetSymbolAddress((void**)&ffhi, g_ffhi);
    cudaGetSymbolAddress((void**)&fflo, g_fflo);
    cudaGetSymbolAddress((void**)&wthi, g_wthi);
    cudaGetSymbolAddress((void**)&wtlo, g_wtlo);

    embed_kernel<<<NTOK, 256>>>(ids, emb, x);

    dim3 gP(Dd / 128, NTOK / 128);      // (8, 32)
    dim3 gF1(FFd / 128, NTOK / 128);    // (32, 32)
    dim3 gTd(Dd / 32, Dd / 32);
    dim3 gT1(FFd / 32, Dd / 32);
    dim3 gT2(Dd / 32, FFd / 32);
    dim3 gQK(Ss / 64, Ss / 64, Bb * Hh);
    dim3 gPV(Ss / 64, Bb * Hh);

    for (int l = 0; l < Ll; l++) {
        size_t wOff = (size_t)l * Dd * Dd;
        ln_kernel<true><<<NTOK, 256>>>(x, ln1g + l * Dd, ln1b + l * Dd, nullptr, hhi, hlo);

        transpose_split<<<gTd, 256>>>(wq + wOff, wthi, wtlo, Dd, Dd);
        mma_gemm<false, false, false><<<gP, 256>>>(hhi, hlo, wthi, wtlo, bq + l * Dd,
                                                   nullptr, q, nullptr, nullptr, NTOK, Dd, Dd);
        transpose_split<<<gTd, 256>>>(wk + wOff, wthi, wtlo, Dd, Dd);
        mma_gemm<false, false, false><<<gP, 256>>>(hhi, hlo, wthi, wtlo, bk + l * Dd,
                                                   nullptr, k, nullptr, nullptr, NTOK, Dd, Dd);
        transpose_split<<<gTd, 256>>>(wv + wOff, wthi, wtlo, Dd, Dd);
        mma_gemm<false, false, false><<<gP, 256>>>(hhi, hlo, wthi, wtlo, bv + l * Dd,
                                                   nullptr, v, nullptr, nullptr, NTOK, Dd, Dd);

        qk_kernel<<<gQK, 256>>>(q, k, am, sc);
        softmax_kernel<<<Bb * Hh * Ss, 256>>>(sc);
        pv_kernel<<<gPV, 256>>>(sc, v, athi, atlo);

        transpose_split<<<gTd, 256>>>(wo + wOff, wthi, wtlo, Dd, Dd);
        mma_gemm<false, true, false><<<gP, 256>>>(athi, atlo, wthi, wtlo, bo + l * Dd,
                                                  x, x, nullptr, nullptr, NTOK, Dd, Dd);

        ln_kernel<true><<<NTOK, 256>>>(x, ln2g + l * Dd, ln2b + l * Dd, nullptr, hhi, hlo);

        transpose_split<<<gT1, 256>>>(w1 + (size_t)l * Dd * FFd, wthi, wtlo, Dd, FFd);
        mma_gemm<true, false, true><<<gF1, 256>>>(hhi, hlo, wthi, wtlo, b1 + l * FFd,
                                                  nullptr, nullptr, ffhi, fflo, NTOK, FFd, Dd);
        transpose_split<<<gT2, 256>>>(w2 + (size_t)l * FFd * Dd, wthi, wtlo, FFd, Dd);
        mma_gemm<false, true, false><<<gP, 256>>>(ffhi, fflo, wthi, wtlo, b2 + l * Dd,
                                                  x, x, nullptr, nullptr, NTOK, Dd, FFd);
    }
    ln_kernel<false><<<NTOK, 256>>>(x, lnfg, lnfb, (float*)d_out, nullptr, nullptr);
}